// round 12
// baseline (speedup 1.0000x reference)
#include <cuda_runtime.h>
#include <math.h>

// Problem constants
#define Bsz 2
#define Tn  1024
#define En  512
#define Hn  8
#define Dn  64
#define TC  64                 // chunk length
#define NCH (Tn / TC)          // 16 chunks
#define NBH (Bsz * Hn)         // 16 (b,h) pairs
#define STATE_STRIDE 8320      // Scos(4096) + Ssin(4096) + zc(64) + zs(64)
#define PI_2f 1.5707963267948966f
#define EPSf  1e-6f

// ---------------- scratch (no runtime allocation allowed) ----------------
__device__ float g_qkv[Bsz * Tn * 3 * En];                 // [2048][1536]  12MB
__device__ float g_state[NBH * NCH * STATE_STRIDE];        // 8.1MB
__device__ float g_attn[Bsz * Tn * En];                    // [2048][512]   4MB

// =========================================================================
// K1/K5: C[M,N] = A[M,K] @ B[N,K]^T + bias[N]   (all row-major, NT gemm)
// BM=128, BN=64, BK=16, 256 threads, 8x4 per-thread microtile
// =========================================================================
__global__ __launch_bounds__(256) void sgemm_nt_bias(
    const float* __restrict__ A, const float* __restrict__ Bm,
    const float* __restrict__ bias, float* __restrict__ C,
    int M, int N, int K)
{
    __shared__ float As[16][128];
    __shared__ float Bs[16][64];

    const int tid = threadIdx.x;
    const int m0 = blockIdx.y * 128;
    const int n0 = blockIdx.x * 64;
    const int ty = tid >> 4;         // 0..15
    const int tx = tid & 15;         // 0..15

    float acc[8][4];
#pragma unroll
    for (int i = 0; i < 8; i++)
#pragma unroll
        for (int j = 0; j < 4; j++) acc[i][j] = 0.f;

    for (int k0 = 0; k0 < K; k0 += 16) {
        // load A tile 128x16 (coalesced float4, transpose into As[k][m])
#pragma unroll
        for (int it = 0; it < 2; it++) {
            int idx = it * 256 + tid;
            int row = idx >> 2, quad = idx & 3;
            float4 a = *reinterpret_cast<const float4*>(&A[(size_t)(m0 + row) * K + k0 + quad * 4]);
            As[quad * 4 + 0][row] = a.x;
            As[quad * 4 + 1][row] = a.y;
            As[quad * 4 + 2][row] = a.z;
            As[quad * 4 + 3][row] = a.w;
        }
        // load B tile 64x16
        {
            int row = tid >> 2, quad = tid & 3;
            float4 b = *reinterpret_cast<const float4*>(&Bm[(size_t)(n0 + row) * K + k0 + quad * 4]);
            Bs[quad * 4 + 0][row] = b.x;
            Bs[quad * 4 + 1][row] = b.y;
            Bs[quad * 4 + 2][row] = b.z;
            Bs[quad * 4 + 3][row] = b.w;
        }
        __syncthreads();

#pragma unroll
        for (int kk = 0; kk < 16; kk++) {
            float4 a0 = *reinterpret_cast<const float4*>(&As[kk][ty * 8]);
            float4 a1 = *reinterpret_cast<const float4*>(&As[kk][ty * 8 + 4]);
            float4 b0 = *reinterpret_cast<const float4*>(&Bs[kk][tx * 4]);
            float av[8] = {a0.x, a0.y, a0.z, a0.w, a1.x, a1.y, a1.z, a1.w};
            float bv[4] = {b0.x, b0.y, b0.z, b0.w};
#pragma unroll
            for (int i = 0; i < 8; i++)
#pragma unroll
                for (int j = 0; j < 4; j++)
                    acc[i][j] = fmaf(av[i], bv[j], acc[i][j]);
        }
        __syncthreads();
    }

    float4 bb = *reinterpret_cast<const float4*>(&bias[n0 + tx * 4]);
    float bv[4] = {bb.x, bb.y, bb.z, bb.w};
#pragma unroll
    for (int i = 0; i < 8; i++) {
        float4 o;
        o.x = acc[i][0] + bv[0];
        o.y = acc[i][1] + bv[1];
        o.z = acc[i][2] + bv[2];
        o.w = acc[i][3] + bv[3];
        *reinterpret_cast<float4*>(&C[(size_t)(m0 + ty * 8 + i) * N + n0 + tx * 4]) = o;
    }
}

// =========================================================================
// K2: per-chunk state sums. grid = NBH*NCH (256) blocks, 256 threads.
//   Scos[d][e] = sum_s k'[s,d]*cos_s*v[s,e] ; Ssin likewise ; zc/zs = col sums
// =========================================================================
__global__ __launch_bounds__(256) void chunk_sums_kernel()
{
    const int blk = blockIdx.x;
    const int bh = blk / NCH, c = blk % NCH;
    const int b = bh / Hn, h = bh % Hn;

    __shared__ float kc[Dn], ks[Dn], vv[Dn];

    const int tid = threadIdx.x;
    const int d4 = (tid >> 4) * 4;
    const int e4 = (tid & 15) * 4;

    float Sc[4][4], Ss[4][4];
#pragma unroll
    for (int i = 0; i < 4; i++)
#pragma unroll
        for (int j = 0; j < 4; j++) { Sc[i][j] = 0.f; Ss[i][j] = 0.f; }
    float zc = 0.f, zs = 0.f;

    for (int s = 0; s < TC; s++) {
        const int tg = c * TC + s;
        const size_t row = (size_t)(b * Tn + tg) * (3 * En);
        if (tid < Dn) {
            float kraw = g_qkv[row + En + h * Dn + tid];
            float kp = fmaxf(kraw, 0.f);
            float ang = PI_2f * (float)tg / (float)Tn;
            float si, co;
            sincosf(ang, &si, &co);
            kc[tid] = kp * co;
            ks[tid] = kp * si;
        } else if (tid < 2 * Dn) {
            vv[tid - Dn] = g_qkv[row + 2 * En + h * Dn + (tid - Dn)];
        }
        __syncthreads();

        float4 v4  = *reinterpret_cast<const float4*>(&vv[e4]);
        float4 kc4 = *reinterpret_cast<const float4*>(&kc[d4]);
        float4 ks4 = *reinterpret_cast<const float4*>(&ks[d4]);
        float va[4] = {v4.x, v4.y, v4.z, v4.w};
        float ca[4] = {kc4.x, kc4.y, kc4.z, kc4.w};
        float sa[4] = {ks4.x, ks4.y, ks4.z, ks4.w};
#pragma unroll
        for (int i = 0; i < 4; i++)
#pragma unroll
            for (int j = 0; j < 4; j++) {
                Sc[i][j] = fmaf(ca[i], va[j], Sc[i][j]);
                Ss[i][j] = fmaf(sa[i], va[j], Ss[i][j]);
            }
        if (tid < Dn) { zc += kc[tid]; zs += ks[tid]; }
        __syncthreads();
    }

    float* st = g_state + (size_t)blk * STATE_STRIDE;
#pragma unroll
    for (int i = 0; i < 4; i++)
#pragma unroll
        for (int j = 0; j < 4; j++) {
            st[(d4 + i) * Dn + e4 + j]        = Sc[i][j];
            st[4096 + (d4 + i) * Dn + e4 + j] = Ss[i][j];
        }
    if (tid < Dn) { st[8192 + tid] = zc; st[8256 + tid] = zs; }
}

// =========================================================================
// K3: exclusive prefix scan over chunks (in place). grid = NBH, 256 threads
// =========================================================================
__global__ __launch_bounds__(256) void scan_states_kernel()
{
    const int bh = blockIdx.x;
    const int tid = threadIdx.x;
    float acc[33];
#pragma unroll
    for (int j = 0; j < 33; j++) acc[j] = 0.f;

    float* base = g_state + (size_t)bh * NCH * STATE_STRIDE;
    for (int c = 0; c < NCH; c++) {
        float* st = base + (size_t)c * STATE_STRIDE;
#pragma unroll
        for (int j = 0; j < 33; j++) {
            int idx = tid + j * 256;
            if (idx < STATE_STRIDE) {
                float t = st[idx];
                st[idx] = acc[j];
                acc[j] += t;
            }
        }
    }
}

// =========================================================================
// K4: per-chunk attention output. grid = NBH*NCH (256), 256 threads.
// ctx[t][e] = qcos[t]·Pcos[:,e] + qsin[t]·Psin[:,e]
//           + sum_{s<=t} (q'[t]·k'[s]) cos(ang_t-ang_s) v[s][e]
// out = ctx / (norm + eps)
// =========================================================================
extern __shared__ float k4_smem[];
__global__ __launch_bounds__(256) void attn_chunk_kernel()
{
    const int blk = blockIdx.x;
    const int bh = blk / NCH, c = blk % NCH;
    const int b = bh / Hn, h = bh % Hn;

    float* Qt   = k4_smem;            // [64][68]  Qt[d][t] = relu(q)
    float* Kt   = Qt + 64 * 68;       // [64][68]  Kt[d][s] = relu(k)
    float* Vs   = Kt + 64 * 68;       // [64][64]  Vs[s][e]
    float* Ws   = Vs + 64 * 64;       // [64][64]  W[t][s] (masked)
    float* cosv = Ws + 64 * 64;       // [64]
    float* sinv = cosv + 64;          // [64]
    float* normv = sinv + 64;         // [64]

    const int tid = threadIdx.x;
    const int t4 = (tid >> 4) * 4;
    const int e4 = (tid & 15) * 4;

    // ---- load Q', K', V ----
#pragma unroll
    for (int r = 0; r < 16; r++) {
        int idx = r * 256 + tid;
        int t = idx >> 6, d = idx & 63;
        size_t row = (size_t)(b * Tn + c * TC + t) * (3 * En);
        float qv = fmaxf(g_qkv[row + h * Dn + d], 0.f);
        float kv = fmaxf(g_qkv[row + En + h * Dn + d], 0.f);
        float vv = g_qkv[row + 2 * En + h * Dn + d];
        Qt[d * 68 + t] = qv;
        Kt[d * 68 + t] = kv;
        Vs[t * 64 + d] = vv;
    }
    if (tid < 64) {
        float ang = PI_2f * (float)(c * TC + tid) / (float)Tn;
        float si, co;
        sincosf(ang, &si, &co);
        cosv[tid] = co;
        sinv[tid] = si;
    }
    __syncthreads();

    float ct[4], st4[4], cs[4], ss[4];
#pragma unroll
    for (int i = 0; i < 4; i++) { ct[i] = cosv[t4 + i]; st4[i] = sinv[t4 + i]; }
#pragma unroll
    for (int j = 0; j < 4; j++) { cs[j] = cosv[e4 + j]; ss[j] = sinv[e4 + j]; }

    const float* Pc = g_state + (size_t)blk * STATE_STRIDE;  // exclusive prefix
    const float* Ps = Pc + 4096;

    float ctx[4][4], wacc[4][4];
#pragma unroll
    for (int i = 0; i < 4; i++)
#pragma unroll
        for (int j = 0; j < 4; j++) { ctx[i][j] = 0.f; wacc[i][j] = 0.f; }

    // ---- fused: inter-chunk ctx (q @ P) and raw scores (q @ k^T) ----
#pragma unroll 4
    for (int d = 0; d < 64; d++) {
        float4 q4  = *reinterpret_cast<const float4*>(&Qt[d * 68 + t4]);
        float4 k4  = *reinterpret_cast<const float4*>(&Kt[d * 68 + e4]);
        float4 pc4 = *reinterpret_cast<const float4*>(&Pc[d * 64 + e4]);
        float4 ps4 = *reinterpret_cast<const float4*>(&Ps[d * 64 + e4]);
        float qa[4] = {q4.x, q4.y, q4.z, q4.w};
        float ka[4] = {k4.x, k4.y, k4.z, k4.w};
        float pa[4] = {pc4.x, pc4.y, pc4.z, pc4.w};
        float sa[4] = {ps4.x, ps4.y, ps4.z, ps4.w};
#pragma unroll
        for (int i = 0; i < 4; i++) {
            float qc = qa[i] * ct[i];
            float qs = qa[i] * st4[i];
#pragma unroll
            for (int j = 0; j < 4; j++) {
                wacc[i][j] = fmaf(qa[i], ka[j], wacc[i][j]);
                ctx[i][j]  = fmaf(qc, pa[j], ctx[i][j]);
                ctx[i][j]  = fmaf(qs, sa[j], ctx[i][j]);
            }
        }
    }

    // ---- apply cos(delta) weight + causal mask, write W ----
#pragma unroll
    for (int i = 0; i < 4; i++) {
        int tl = t4 + i;
        float wv[4];
#pragma unroll
        for (int j = 0; j < 4; j++) {
            int sl = e4 + j;
            float f = ct[i] * cs[j] + st4[i] * ss[j];   // cos(ang_t - ang_s)
            wv[j] = (sl <= tl) ? wacc[i][j] * f : 0.f;
        }
        float4 o = {wv[0], wv[1], wv[2], wv[3]};
        *reinterpret_cast<float4*>(&Ws[tl * 64 + e4]) = o;
    }

    // ---- norm, inter-chunk part ----
    if (tid < 64) {
        const float* zc = Pc + 8192;
        const float* zs = Pc + 8256;
        float nc = 0.f, ns = 0.f;
#pragma unroll 8
        for (int d = 0; d < 64; d++) {
            float qv = Qt[d * 68 + tid];
            nc = fmaf(qv, zc[d], nc);
            ns = fmaf(qv, zs[d], ns);
        }
        normv[tid] = cosv[tid] * nc + sinv[tid] * ns;
    }
    __syncthreads();

    // ---- norm, intra part (masked entries are zero so sum whole row) ----
    if (tid < 64) {
        float acc = normv[tid];
        const float* wr = &Ws[tid * 64];
#pragma unroll
        for (int s = 0; s < 64; s += 4) {
            float4 w = *reinterpret_cast<const float4*>(&wr[s]);
            acc += w.x + w.y + w.z + w.w;
        }
        normv[tid] = 1.f / (acc + EPSf);
    }

    // ---- intra-chunk ctx += W @ V ----
#pragma unroll 4
    for (int s = 0; s < 64; s++) {
        float4 v4 = *reinterpret_cast<const float4*>(&Vs[s * 64 + e4]);
        float va[4] = {v4.x, v4.y, v4.z, v4.w};
        float wv[4];
#pragma unroll
        for (int i = 0; i < 4; i++) wv[i] = Ws[(t4 + i) * 64 + s];
#pragma unroll
        for (int i = 0; i < 4; i++)
#pragma unroll
            for (int j = 0; j < 4; j++)
                ctx[i][j] = fmaf(wv[i], va[j], ctx[i][j]);
    }
    __syncthreads();

    // ---- normalize and write ----
#pragma unroll
    for (int i = 0; i < 4; i++) {
        float rn = normv[t4 + i];
        float4 o;
        o.x = ctx[i][0] * rn;
        o.y = ctx[i][1] * rn;
        o.z = ctx[i][2] * rn;
        o.w = ctx[i][3] * rn;
        *reinterpret_cast<float4*>(
            &g_attn[(size_t)(b * Tn + c * TC + t4 + i) * En + h * Dn + e4]) = o;
    }
}

// =========================================================================
// launch
// =========================================================================
extern "C" void kernel_launch(void* const* d_in, const int* in_sizes, int n_in,
                              void* d_out, int out_size)
{
    const float* x      = (const float*)d_in[0];
    const float* w_qkv  = (const float*)d_in[1];
    const float* b_qkv  = (const float*)d_in[2];
    const float* w_out  = (const float*)d_in[3];
    const float* b_out  = (const float*)d_in[4];
    float* out = (float*)d_out;

    float *p_qkv = nullptr, *p_attn = nullptr;
    cudaGetSymbolAddress((void**)&p_qkv, g_qkv);
    cudaGetSymbolAddress((void**)&p_attn, g_attn);

    const int K4_SMEM = (2 * 64 * 68 + 2 * 64 * 64 + 3 * 64) * (int)sizeof(float); // 68352
    cudaFuncSetAttribute(attn_chunk_kernel,
                         cudaFuncAttributeMaxDynamicSharedMemorySize, K4_SMEM);

    // 1) qkv = x @ w_qkv^T + b_qkv   [2048 x 1536]
    {
        dim3 grid(3 * En / 64, (Bsz * Tn) / 128);
        sgemm_nt_bias<<<grid, 256>>>(x, w_qkv, b_qkv, p_qkv,
                                     Bsz * Tn, 3 * En, En);
    }
    // 2) per-chunk state sums
    chunk_sums_kernel<<<NBH * NCH, 256>>>();
    // 3) exclusive scan over chunks
    scan_states_kernel<<<NBH, 256>>>();
    // 4) per-chunk attention
    attn_chunk_kernel<<<NBH * NCH, 256, K4_SMEM>>>();
    // 5) out = attn @ w_out^T + b_out   [2048 x 512]
    {
        dim3 grid(En / 64, (Bsz * Tn) / 128);
        sgemm_nt_bias<<<grid, 256>>>(p_attn, w_out, b_out, out,
                                     Bsz * Tn, En, En);
    }
}

// round 13
// speedup vs baseline: 1.0242x; 1.0242x over previous
#include <cuda_runtime.h>
#include <math.h>

// Problem constants
#define Bsz 2
#define Tn  1024
#define En  512
#define Hn  8
#define Dn  64
#define TC  64                 // chunk length
#define NCH (Tn / TC)          // 16 chunks
#define NBH (Bsz * Hn)         // 16 (b,h) pairs
#define STATE_STRIDE 8320      // Scos(4096) + Ssin(4096) + zc(64) + zs(64)
#define PI_2f 1.5707963267948966f
#define EPSf  1e-6f

// ---------------- scratch (no runtime allocation allowed) ----------------
__device__ float g_qkv[Bsz * Tn * 3 * En];                 // [2048][1536]  12MB
__device__ float g_state[NBH * NCH * STATE_STRIDE];        // 8.1MB
__device__ float g_attn[Bsz * Tn * En];                    // [2048][512]   4MB

// =========================================================================
// K1/K5: C[M,N] = A[M,K] @ B[N,K]^T + bias[N]   (all row-major, NT gemm)
// BM=128, BN=64, BK=16, 256 threads, 8x4 per-thread microtile
// =========================================================================
__global__ __launch_bounds__(256) void sgemm_nt_bias(
    const float* __restrict__ A, const float* __restrict__ Bm,
    const float* __restrict__ bias, float* __restrict__ C,
    int M, int N, int K)
{
    __shared__ float As[16][128];
    __shared__ float Bs[16][64];

    const int tid = threadIdx.x;
    const int m0 = blockIdx.y * 128;
    const int n0 = blockIdx.x * 64;
    const int ty = tid >> 4;         // 0..15
    const int tx = tid & 15;         // 0..15

    float acc[8][4];
#pragma unroll
    for (int i = 0; i < 8; i++)
#pragma unroll
        for (int j = 0; j < 4; j++) acc[i][j] = 0.f;

    for (int k0 = 0; k0 < K; k0 += 16) {
        // load A tile 128x16 (coalesced float4, transpose into As[k][m])
#pragma unroll
        for (int it = 0; it < 2; it++) {
            int idx = it * 256 + tid;
            int row = idx >> 2, quad = idx & 3;
            float4 a = *reinterpret_cast<const float4*>(&A[(size_t)(m0 + row) * K + k0 + quad * 4]);
            As[quad * 4 + 0][row] = a.x;
            As[quad * 4 + 1][row] = a.y;
            As[quad * 4 + 2][row] = a.z;
            As[quad * 4 + 3][row] = a.w;
        }
        // load B tile 64x16
        {
            int row = tid >> 2, quad = tid & 3;
            float4 b = *reinterpret_cast<const float4*>(&Bm[(size_t)(n0 + row) * K + k0 + quad * 4]);
            Bs[quad * 4 + 0][row] = b.x;
            Bs[quad * 4 + 1][row] = b.y;
            Bs[quad * 4 + 2][row] = b.z;
            Bs[quad * 4 + 3][row] = b.w;
        }
        __syncthreads();

#pragma unroll
        for (int kk = 0; kk < 16; kk++) {
            float4 a0 = *reinterpret_cast<const float4*>(&As[kk][ty * 8]);
            float4 a1 = *reinterpret_cast<const float4*>(&As[kk][ty * 8 + 4]);
            float4 b0 = *reinterpret_cast<const float4*>(&Bs[kk][tx * 4]);
            float av[8] = {a0.x, a0.y, a0.z, a0.w, a1.x, a1.y, a1.z, a1.w};
            float bv[4] = {b0.x, b0.y, b0.z, b0.w};
#pragma unroll
            for (int i = 0; i < 8; i++)
#pragma unroll
                for (int j = 0; j < 4; j++)
                    acc[i][j] = fmaf(av[i], bv[j], acc[i][j]);
        }
        __syncthreads();
    }

    float4 bb = *reinterpret_cast<const float4*>(&bias[n0 + tx * 4]);
    float bv[4] = {bb.x, bb.y, bb.z, bb.w};
#pragma unroll
    for (int i = 0; i < 8; i++) {
        float4 o;
        o.x = acc[i][0] + bv[0];
        o.y = acc[i][1] + bv[1];
        o.z = acc[i][2] + bv[2];
        o.w = acc[i][3] + bv[3];
        *reinterpret_cast<float4*>(&C[(size_t)(m0 + ty * 8 + i) * N + n0 + tx * 4]) = o;
    }
}

// =========================================================================
// K2: per-chunk state sums. grid = NBH*NCH (256) blocks, 256 threads.
//   Scos[d][e] = sum_s k'[s,d]*cos_s*v[s,e] ; Ssin likewise ; zc/zs = col sums
// =========================================================================
__global__ __launch_bounds__(256) void chunk_sums_kernel()
{
    const int blk = blockIdx.x;
    const int bh = blk / NCH, c = blk % NCH;
    const int b = bh / Hn, h = bh % Hn;

    __shared__ float kc[Dn], ks[Dn], vv[Dn];

    const int tid = threadIdx.x;
    const int d4 = (tid >> 4) * 4;
    const int e4 = (tid & 15) * 4;

    float Sc[4][4], Ss[4][4];
#pragma unroll
    for (int i = 0; i < 4; i++)
#pragma unroll
        for (int j = 0; j < 4; j++) { Sc[i][j] = 0.f; Ss[i][j] = 0.f; }
    float zc = 0.f, zs = 0.f;

    for (int s = 0; s < TC; s++) {
        const int tg = c * TC + s;
        const size_t row = (size_t)(b * Tn + tg) * (3 * En);
        if (tid < Dn) {
            float kraw = g_qkv[row + En + h * Dn + tid];
            float kp = fmaxf(kraw, 0.f);
            float ang = PI_2f * (float)tg / (float)Tn;
            float si, co;
            sincosf(ang, &si, &co);
            kc[tid] = kp * co;
            ks[tid] = kp * si;
        } else if (tid < 2 * Dn) {
            vv[tid - Dn] = g_qkv[row + 2 * En + h * Dn + (tid - Dn)];
        }
        __syncthreads();

        float4 v4  = *reinterpret_cast<const float4*>(&vv[e4]);
        float4 kc4 = *reinterpret_cast<const float4*>(&kc[d4]);
        float4 ks4 = *reinterpret_cast<const float4*>(&ks[d4]);
        float va[4] = {v4.x, v4.y, v4.z, v4.w};
        float ca[4] = {kc4.x, kc4.y, kc4.z, kc4.w};
        float sa[4] = {ks4.x, ks4.y, ks4.z, ks4.w};
#pragma unroll
        for (int i = 0; i < 4; i++)
#pragma unroll
            for (int j = 0; j < 4; j++) {
                Sc[i][j] = fmaf(ca[i], va[j], Sc[i][j]);
                Ss[i][j] = fmaf(sa[i], va[j], Ss[i][j]);
            }
        if (tid < Dn) { zc += kc[tid]; zs += ks[tid]; }
        __syncthreads();
    }

    float* st = g_state + (size_t)blk * STATE_STRIDE;
#pragma unroll
    for (int i = 0; i < 4; i++)
#pragma unroll
        for (int j = 0; j < 4; j++) {
            st[(d4 + i) * Dn + e4 + j]        = Sc[i][j];
            st[4096 + (d4 + i) * Dn + e4 + j] = Ss[i][j];
        }
    if (tid < Dn) { st[8192 + tid] = zc; st[8256 + tid] = zs; }
}

// =========================================================================
// K3: exclusive prefix scan over chunks (in place). grid = NBH, 256 threads
// =========================================================================
__global__ __launch_bounds__(256) void scan_states_kernel()
{
    const int bh = blockIdx.x;
    const int tid = threadIdx.x;
    float acc[33];
#pragma unroll
    for (int j = 0; j < 33; j++) acc[j] = 0.f;

    float* base = g_state + (size_t)bh * NCH * STATE_STRIDE;
    for (int c = 0; c < NCH; c++) {
        float* st = base + (size_t)c * STATE_STRIDE;
#pragma unroll
        for (int j = 0; j < 33; j++) {
            int idx = tid + j * 256;
            if (idx < STATE_STRIDE) {
                float t = st[idx];
                st[idx] = acc[j];
                acc[j] += t;
            }
        }
    }
}

// =========================================================================
// K4: per-chunk attention output. grid = NBH*NCH (256), 256 threads.
// ctx[t][e] = qcos[t]·Pcos[:,e] + qsin[t]·Psin[:,e]
//           + sum_{s<=t} (q'[t]·k'[s]) cos(ang_t-ang_s) v[s][e]
// out = ctx / (norm + eps)
// =========================================================================
extern __shared__ float k4_smem[];
__global__ __launch_bounds__(256) void attn_chunk_kernel()
{
    const int blk = blockIdx.x;
    const int bh = blk / NCH, c = blk % NCH;
    const int b = bh / Hn, h = bh % Hn;

    float* Qt   = k4_smem;            // [64][68]  Qt[d][t] = relu(q)
    float* Kt   = Qt + 64 * 68;       // [64][68]  Kt[d][s] = relu(k)
    float* Vs   = Kt + 64 * 68;       // [64][64]  Vs[s][e]
    float* Ws   = Vs + 64 * 64;       // [64][64]  W[t][s] (masked)
    float* cosv = Ws + 64 * 64;       // [64]
    float* sinv = cosv + 64;          // [64]
    float* normv = sinv + 64;         // [64]

    const int tid = threadIdx.x;
    const int t4 = (tid >> 4) * 4;
    const int e4 = (tid & 15) * 4;

    // ---- load Q', K', V ----
#pragma unroll
    for (int r = 0; r < 16; r++) {
        int idx = r * 256 + tid;
        int t = idx >> 6, d = idx & 63;
        size_t row = (size_t)(b * Tn + c * TC + t) * (3 * En);
        float qv = fmaxf(g_qkv[row + h * Dn + d], 0.f);
        float kv = fmaxf(g_qkv[row + En + h * Dn + d], 0.f);
        float vv = g_qkv[row + 2 * En + h * Dn + d];
        Qt[d * 68 + t] = qv;
        Kt[d * 68 + t] = kv;
        Vs[t * 64 + d] = vv;
    }
    if (tid < 64) {
        float ang = PI_2f * (float)(c * TC + tid) / (float)Tn;
        float si, co;
        sincosf(ang, &si, &co);
        cosv[tid] = co;
        sinv[tid] = si;
    }
    __syncthreads();

    float ct[4], st4[4], cs[4], ss[4];
#pragma unroll
    for (int i = 0; i < 4; i++) { ct[i] = cosv[t4 + i]; st4[i] = sinv[t4 + i]; }
#pragma unroll
    for (int j = 0; j < 4; j++) { cs[j] = cosv[e4 + j]; ss[j] = sinv[e4 + j]; }

    const float* Pc = g_state + (size_t)blk * STATE_STRIDE;  // exclusive prefix
    const float* Ps = Pc + 4096;

    float ctx[4][4], wacc[4][4];
#pragma unroll
    for (int i = 0; i < 4; i++)
#pragma unroll
        for (int j = 0; j < 4; j++) { ctx[i][j] = 0.f; wacc[i][j] = 0.f; }

    // ---- fused: inter-chunk ctx (q @ P) and raw scores (q @ k^T) ----
#pragma unroll 4
    for (int d = 0; d < 64; d++) {
        float4 q4  = *reinterpret_cast<const float4*>(&Qt[d * 68 + t4]);
        float4 k4  = *reinterpret_cast<const float4*>(&Kt[d * 68 + e4]);
        float4 pc4 = *reinterpret_cast<const float4*>(&Pc[d * 64 + e4]);
        float4 ps4 = *reinterpret_cast<const float4*>(&Ps[d * 64 + e4]);
        float qa[4] = {q4.x, q4.y, q4.z, q4.w};
        float ka[4] = {k4.x, k4.y, k4.z, k4.w};
        float pa[4] = {pc4.x, pc4.y, pc4.z, pc4.w};
        float sa[4] = {ps4.x, ps4.y, ps4.z, ps4.w};
#pragma unroll
        for (int i = 0; i < 4; i++) {
            float qc = qa[i] * ct[i];
            float qs = qa[i] * st4[i];
#pragma unroll
            for (int j = 0; j < 4; j++) {
                wacc[i][j] = fmaf(qa[i], ka[j], wacc[i][j]);
                ctx[i][j]  = fmaf(qc, pa[j], ctx[i][j]);
                ctx[i][j]  = fmaf(qs, sa[j], ctx[i][j]);
            }
        }
    }

    // ---- apply cos(delta) weight + causal mask, write W ----
#pragma unroll
    for (int i = 0; i < 4; i++) {
        int tl = t4 + i;
        float wv[4];
#pragma unroll
        for (int j = 0; j < 4; j++) {
            int sl = e4 + j;
            float f = ct[i] * cs[j] + st4[i] * ss[j];   // cos(ang_t - ang_s)
            wv[j] = (sl <= tl) ? wacc[i][j] * f : 0.f;
        }
        float4 o = {wv[0], wv[1], wv[2], wv[3]};
        *reinterpret_cast<float4*>(&Ws[tl * 64 + e4]) = o;
    }

    // ---- norm, inter-chunk part ----
    if (tid < 64) {
        const float* zc = Pc + 8192;
        const float* zs = Pc + 8256;
        float nc = 0.f, ns = 0.f;
#pragma unroll 8
        for (int d = 0; d < 64; d++) {
            float qv = Qt[d * 68 + tid];
            nc = fmaf(qv, zc[d], nc);
            ns = fmaf(qv, zs[d], ns);
        }
        normv[tid] = cosv[tid] * nc + sinv[tid] * ns;
    }
    __syncthreads();

    // ---- norm, intra part (masked entries are zero so sum whole row) ----
    if (tid < 64) {
        float acc = normv[tid];
        const float* wr = &Ws[tid * 64];
#pragma unroll
        for (int s = 0; s < 64; s += 4) {
            float4 w = *reinterpret_cast<const float4*>(&wr[s]);
            acc += w.x + w.y + w.z + w.w;
        }
        normv[tid] = 1.f / (acc + EPSf);
    }

    // ---- intra-chunk ctx += W @ V ----
#pragma unroll 4
    for (int s = 0; s < 64; s++) {
        float4 v4 = *reinterpret_cast<const float4*>(&Vs[s * 64 + e4]);
        float va[4] = {v4.x, v4.y, v4.z, v4.w};
        float wv[4];
#pragma unroll
        for (int i = 0; i < 4; i++) wv[i] = Ws[(t4 + i) * 64 + s];
#pragma unroll
        for (int i = 0; i < 4; i++)
#pragma unroll
            for (int j = 0; j < 4; j++)
                ctx[i][j] = fmaf(wv[i], va[j], ctx[i][j]);
    }
    __syncthreads();

    // ---- normalize and write ----
#pragma unroll
    for (int i = 0; i < 4; i++) {
        float rn = normv[t4 + i];
        float4 o;
        o.x = ctx[i][0] * rn;
        o.y = ctx[i][1] * rn;
        o.z = ctx[i][2] * rn;
        o.w = ctx[i][3] * rn;
        *reinterpret_cast<float4*>(
            &g_attn[(size_t)(b * Tn + c * TC + t4 + i) * En + h * Dn + e4]) = o;
    }
}

// =========================================================================
// launch
// =========================================================================
extern "C" void kernel_launch(void* const* d_in, const int* in_sizes, int n_in,
                              void* d_out, int out_size)
{
    const float* x      = (const float*)d_in[0];
    const float* w_qkv  = (const float*)d_in[1];
    const float* b_qkv  = (const float*)d_in[2];
    const float* w_out  = (const float*)d_in[3];
    const float* b_out  = (const float*)d_in[4];
    float* out = (float*)d_out;

    float *p_qkv = nullptr, *p_attn = nullptr;
    cudaGetSymbolAddress((void**)&p_qkv, g_qkv);
    cudaGetSymbolAddress((void**)&p_attn, g_attn);

    const int K4_SMEM = (2 * 64 * 68 + 2 * 64 * 64 + 3 * 64) * (int)sizeof(float); // 68352
    cudaFuncSetAttribute(attn_chunk_kernel,
                         cudaFuncAttributeMaxDynamicSharedMemorySize, K4_SMEM);

    // 1) qkv = x @ w_qkv^T + b_qkv   [2048 x 1536]
    {
        dim3 grid(3 * En / 64, (Bsz * Tn) / 128);
        sgemm_nt_bias<<<grid, 256>>>(x, w_qkv, b_qkv, p_qkv,
                                     Bsz * Tn, 3 * En, En);
    }
    // 2) per-chunk state sums
    chunk_sums_kernel<<<NBH * NCH, 256>>>();
    // 3) exclusive scan over chunks
    scan_states_kernel<<<NBH, 256>>>();
    // 4) per-chunk attention
    attn_chunk_kernel<<<NBH * NCH, 256, K4_SMEM>>>();
    // 5) out = attn @ w_out^T + b_out   [2048 x 512]
    {
        dim3 grid(En / 64, (Bsz * Tn) / 128);
        sgemm_nt_bias<<<grid, 256>>>(p_attn, w_out, b_out, out,
                                     Bsz * Tn, En, En);
    }
}